// round 14
// baseline (speedup 1.0000x reference)
#include <cuda_runtime.h>
#include <stdint.h>
#include <math.h>

#define B   8
#define T   2048
#define EMB 1024
#define H   128
#define BT  (B*T)

// Scratch for Q/K/V projections (no cudaMalloc allowed).
__device__ float g_q[BT * H];
__device__ float g_k[BT * H];
__device__ float g_v[BT * H];

// ---------------------------------------------------------------------------
// Helpers: tf32 convert + m16n8k8 tf32 MMA (fp32 accumulate)
// ---------------------------------------------------------------------------
__device__ __forceinline__ uint32_t f2tf32(float f) {
    uint32_t u;
    asm volatile("cvt.rna.tf32.f32 %0, %1;" : "=r"(u) : "f"(f));
    return u;
}

__device__ __forceinline__ void mma_tf32(
    float& d0, float& d1, float& d2, float& d3,
    uint32_t a0, uint32_t a1, uint32_t a2, uint32_t a3,
    uint32_t b0, uint32_t b1)
{
    asm volatile(
        "mma.sync.aligned.m16n8k8.row.col.f32.tf32.tf32.f32 "
        "{%0,%1,%2,%3}, {%4,%5,%6,%7}, {%8,%9}, {%0,%1,%2,%3};"
        : "+f"(d0), "+f"(d1), "+f"(d2), "+f"(d3)
        : "r"(a0), "r"(a1), "r"(a2), "r"(a3), "r"(b0), "r"(b1));
}

// ---------------------------------------------------------------------------
// Projection GEMM (mma.sync tf32): out[16384,128] = x[16384,1024] @ W[1024,128]
// CTA tile 128x128, BK=32, 256 threads = 8 warps (4 M x 2 N).
// Pair-packed smem (uint2 = {elem k, elem k+4}) -> all fragment loads LDS.64.
// Double-buffered: prefetch chunk c+1 into registers before chunk-c MMAs,
// STS after, one __syncthreads per chunk. No occupancy cap (avoid spills).
// ---------------------------------------------------------------------------
#define XS2_STRIDE 20    // uint2 per row (16 + 4 pad): 40 words, mod32 = 8
#define WS2_STRIDE 132   // uint2 per pair-row:        264 words, mod32 = 8
#define PJ_XS  (128 * XS2_STRIDE)            // 2560 u2 per buffer
#define PJ_WS  (16 * WS2_STRIDE)             // 2112 u2 per buffer
#define PJ_BUF (PJ_XS + PJ_WS)               // 4672 u2
#define PJ_SMEM_BYTES (2 * PJ_BUF * 8)       // 74752

__global__ __launch_bounds__(256) void proj_kernel(
    const float* __restrict__ x,
    const float* __restrict__ Wq,
    const float* __restrict__ Wk,
    const float* __restrict__ Wv)
{
    extern __shared__ uint2 psm[];

    const float* __restrict__ W;
    float* out;
    if (blockIdx.y == 0)      { W = Wq; out = g_q; }
    else if (blockIdx.y == 1) { W = Wk; out = g_k; }
    else                      { W = Wv; out = g_v; }

    const int row0 = blockIdx.x * 128;
    const int tid  = threadIdx.x;
    const int warp = tid >> 5, lane = tid & 31;
    const int g = lane >> 2, t = lane & 3;
    const int wm = warp >> 1, wn = warp & 1;      // warp tile: 32 rows x 64 cols

    // prefetch registers
    float4 rx[2][2];        // x: 2 slots x {v0, v1}
    float4 rw[2][2];        // W: 2 slots x {a, b2}

    // slot coords (fixed per thread)
    const int xr0  = tid >> 2,  xksg = tid & 3;           // slot p=0
    const int xr1  = (tid + 256) >> 2;                    // slot p=1 (same ksg)
    const int wpr0 = tid >> 5,  wn40 = (tid & 31) * 4;    // slot p=0
    const int wpr1 = (tid + 256) >> 5;                    // slot p=1 (same n4)

    auto prefetch = [&](int kk) {
        const float* s0 = &x[(size_t)(row0 + xr0) * EMB + kk + xksg * 8];
        rx[0][0] = *(const float4*)s0;
        rx[0][1] = *(const float4*)(s0 + 4);
        const float* s1 = &x[(size_t)(row0 + xr1) * EMB + kk + xksg * 8];
        rx[1][0] = *(const float4*)s1;
        rx[1][1] = *(const float4*)(s1 + 4);
        {
            int ks = wpr0 >> 2, tt = wpr0 & 3;
            const float* w0 = &W[(size_t)(kk + ks * 8 + tt) * H + wn40];
            rw[0][0] = *(const float4*)w0;
            rw[0][1] = *(const float4*)(w0 + 4 * H);
        }
        {
            int ks = wpr1 >> 2, tt = wpr1 & 3;
            const float* w1 = &W[(size_t)(kk + ks * 8 + tt) * H + wn40];
            rw[1][0] = *(const float4*)w1;
            rw[1][1] = *(const float4*)(w1 + 4 * H);
        }
    };

    auto sts_chunk = [&](int buf) {
        uint2* xs = psm + buf * PJ_BUF;
        uint2* ws = xs + PJ_XS;
        {
            uint2* dst = &xs[xr0 * XS2_STRIDE + xksg * 4];
            dst[0] = make_uint2(f2tf32(rx[0][0].x), f2tf32(rx[0][1].x));
            dst[1] = make_uint2(f2tf32(rx[0][0].y), f2tf32(rx[0][1].y));
            dst[2] = make_uint2(f2tf32(rx[0][0].z), f2tf32(rx[0][1].z));
            dst[3] = make_uint2(f2tf32(rx[0][0].w), f2tf32(rx[0][1].w));
            dst = &xs[xr1 * XS2_STRIDE + xksg * 4];
            dst[0] = make_uint2(f2tf32(rx[1][0].x), f2tf32(rx[1][1].x));
            dst[1] = make_uint2(f2tf32(rx[1][0].y), f2tf32(rx[1][1].y));
            dst[2] = make_uint2(f2tf32(rx[1][0].z), f2tf32(rx[1][1].z));
            dst[3] = make_uint2(f2tf32(rx[1][0].w), f2tf32(rx[1][1].w));
        }
        {
            uint2* dst = &ws[wpr0 * WS2_STRIDE + wn40];
            dst[0] = make_uint2(f2tf32(rw[0][0].x), f2tf32(rw[0][1].x));
            dst[1] = make_uint2(f2tf32(rw[0][0].y), f2tf32(rw[0][1].y));
            dst[2] = make_uint2(f2tf32(rw[0][0].z), f2tf32(rw[0][1].z));
            dst[3] = make_uint2(f2tf32(rw[0][0].w), f2tf32(rw[0][1].w));
            dst = &ws[wpr1 * WS2_STRIDE + wn40];
            dst[0] = make_uint2(f2tf32(rw[1][0].x), f2tf32(rw[1][1].x));
            dst[1] = make_uint2(f2tf32(rw[1][0].y), f2tf32(rw[1][1].y));
            dst[2] = make_uint2(f2tf32(rw[1][0].z), f2tf32(rw[1][1].z));
            dst[3] = make_uint2(f2tf32(rw[1][0].w), f2tf32(rw[1][1].w));
        }
    };

    float c[2][8][4];
    #pragma unroll
    for (int i = 0; i < 2; i++)
        #pragma unroll
        for (int j = 0; j < 8; j++)
            c[i][j][0] = c[i][j][1] = c[i][j][2] = c[i][j][3] = 0.f;

    prefetch(0);
    sts_chunk(0);
    __syncthreads();

    for (int cidx = 0; cidx < 32; cidx++) {
        if (cidx < 31) prefetch((cidx + 1) * 32);   // LDGs overlap MMAs below

        uint2* xs = psm + (cidx & 1) * PJ_BUF;
        uint2* ws = xs + PJ_XS;
        #pragma unroll
        for (int ks = 0; ks < 4; ks++) {
            uint2 A[2][2];
            #pragma unroll
            for (int i = 0; i < 2; i++) {
                int rb = wm * 32 + i * 16;
                A[i][0] = xs[(rb + g) * XS2_STRIDE + ks * 4 + t];
                A[i][1] = xs[(rb + g + 8) * XS2_STRIDE + ks * 4 + t];
            }
            #pragma unroll
            for (int j = 0; j < 8; j++) {
                uint2 bb = ws[(ks * 4 + t) * WS2_STRIDE + wn * 64 + j * 8 + g];
                #pragma unroll
                for (int i = 0; i < 2; i++)
                    mma_tf32(c[i][j][0], c[i][j][1], c[i][j][2], c[i][j][3],
                             A[i][0].x, A[i][1].x, A[i][0].y, A[i][1].y,
                             bb.x, bb.y);
            }
        }

        if (cidx < 31) {
            sts_chunk((cidx + 1) & 1);
            __syncthreads();
        }
    }

    #pragma unroll
    for (int i = 0; i < 2; i++) {
        int r = row0 + wm * 32 + i * 16 + g;
        #pragma unroll
        for (int j = 0; j < 8; j++) {
            int col = wn * 64 + j * 8 + 2 * t;
            *(float2*)&out[(size_t)r * H + col] =
                make_float2(c[i][j][0], c[i][j][1]);
            *(float2*)&out[(size_t)(r + 8) * H + col] =
                make_float2(c[i][j][2], c[i][j][3]);
        }
    }
}

// ---------------------------------------------------------------------------
// Flash attention (tf32 MMA, pair-packed smem): grid (T/128, B), 8 warps.
// PROVEN version (R5/R8, 156.5us) -- byte-identical. Each warp owns 16 q-rows.
// ---------------------------------------------------------------------------
#define KS2_STRIDE 68
#define VS2_STRIDE 132
#define PS2_STRIDE 36
#define KS2_OFF 0
#define VS2_OFF (64 * KS2_STRIDE)
#define PS2_OFF (VS2_OFF + 32 * VS2_STRIDE)
#define ATTN_SMEM_U2 (PS2_OFF + 128 * PS2_STRIDE)
#define ATTN_SMEM_BYTES (ATTN_SMEM_U2 * 8)
#define QSTAGE_STRIDE 132

__global__ __launch_bounds__(256, 1) void attn_kernel(float* __restrict__ out)
{
    extern __shared__ uint2 sm2[];
    uint2* Ks2 = sm2 + KS2_OFF;
    uint2* Vs2 = sm2 + VS2_OFF;
    uint2* Ps2 = sm2 + PS2_OFF;
    uint32_t* Psw = (uint32_t*)Ps2;

    const int b    = blockIdx.y;
    const int q0   = blockIdx.x * 128;
    const int tid  = threadIdx.x;
    const int warp = tid >> 5, lane = tid & 31;
    const int g = lane >> 2, t = lane & 3;
    const int qr0 = warp * 16;
    const float scale = 0.08838834764831845f;

    uint32_t qa[16][4];
    {
        uint32_t* Qst = (uint32_t*)sm2;
        const float* qsrc = g_q + (size_t)(b * T + q0) * H;
        #pragma unroll
        for (int p = 0; p < 16; p++) {
            int idx = tid + p * 256;
            int r = idx >> 5, c4 = (idx & 31) * 4;
            float4 v = *(const float4*)&qsrc[r * H + c4];
            uint4 u = make_uint4(f2tf32(v.x * scale), f2tf32(v.y * scale),
                                 f2tf32(v.z * scale), f2tf32(v.w * scale));
            *(uint4*)&Qst[r * QSTAGE_STRIDE + c4] = u;
        }
        __syncthreads();
        #pragma unroll
        for (int ks = 0; ks < 16; ks++) {
            int col = ks * 8 + t;
            qa[ks][0] = Qst[(qr0 + g) * QSTAGE_STRIDE + col];
            qa[ks][1] = Qst[(qr0 + g + 8) * QSTAGE_STRIDE + col];
            qa[ks][2] = Qst[(qr0 + g) * QSTAGE_STRIDE + col + 4];
            qa[ks][3] = Qst[(qr0 + g + 8) * QSTAGE_STRIDE + col + 4];
        }
    }

    float o[16][4];
    #pragma unroll
    for (int j = 0; j < 16; j++)
        o[j][0] = o[j][1] = o[j][2] = o[j][3] = 0.f;
    float m0 = -1e30f, m1 = -1e30f, l0 = 0.f, l1 = 0.f;

    const int poff0 = (t & 1) * 4 + (t >> 1);

    for (int t0 = 0; t0 < T; t0 += 64) {
        __syncthreads();
        {
            const float* kp = g_k + (size_t)(b * T + t0) * H;
            const float* vp = g_v + (size_t)(b * T + t0) * H;
            #pragma unroll
            for (int p = 0; p < 4; p++) {
                int idx = tid + p * 256;
                int r = idx >> 4, ksg = idx & 15;
                const float* src = kp + r * H + ksg * 8;
                float4 v0 = *(const float4*)src;
                float4 v1 = *(const float4*)(src + 4);
                uint2* dst = &Ks2[r * KS2_STRIDE + ksg * 4];
                dst[0] = make_uint2(f2tf32(v0.x), f2tf32(v1.x));
                dst[1] = make_uint2(f2tf32(v0.y), f2tf32(v1.y));
                dst[2] = make_uint2(f2tf32(v0.z), f2tf32(v1.z));
                dst[3] = make_uint2(f2tf32(v0.w), f2tf32(v1.w));
            }
            #pragma unroll
            for (int p = 0; p < 4; p++) {
                int idx = tid + p * 256;
                int pr = idx >> 5, n4 = (idx & 31) * 4;
                int ks = pr >> 2, tt = pr & 3;
                const float* s0 = vp + (ks * 8 + tt) * H + n4;
                float4 a = *(const float4*)s0;
                float4 c2 = *(const float4*)(s0 + 4 * H);
                uint2* dst = &Vs2[pr * VS2_STRIDE + n4];
                dst[0] = make_uint2(f2tf32(a.x), f2tf32(c2.x));
                dst[1] = make_uint2(f2tf32(a.y), f2tf32(c2.y));
                dst[2] = make_uint2(f2tf32(a.z), f2tf32(c2.z));
                dst[3] = make_uint2(f2tf32(a.w), f2tf32(c2.w));
            }
        }
        __syncthreads();

        float s[8][4];
        #pragma unroll
        for (int j = 0; j < 8; j++)
            s[j][0] = s[j][1] = s[j][2] = s[j][3] = 0.f;

        #pragma unroll
        for (int ks = 0; ks < 16; ks++) {
            #pragma unroll
            for (int j = 0; j < 8; j++) {
                uint2 kb = Ks2[(j * 8 + g) * KS2_STRIDE + ks * 4 + t];
                mma_tf32(s[j][0], s[j][1], s[j][2], s[j][3],
                         qa[ks][0], qa[ks][1], qa[ks][2], qa[ks][3],
                         kb.x, kb.y);
            }
        }

        float mx0 = -1e30f, mx1 = -1e30f;
        #pragma unroll
        for (int j = 0; j < 8; j++) {
            mx0 = fmaxf(mx0, fmaxf(s[j][0], s[j][1]));
            mx1 = fmaxf(mx1, fmaxf(s[j][2], s[j][3]));
        }
        #pragma unroll
        for (int off = 1; off <= 2; off <<= 1) {
            mx0 = fmaxf(mx0, __shfl_xor_sync(0xffffffffu, mx0, off));
            mx1 = fmaxf(mx1, __shfl_xor_sync(0xffffffffu, mx1, off));
        }
        float mn0 = fmaxf(m0, mx0), mn1 = fmaxf(m1, mx1);
        float cr0 = __expf(m0 - mn0), cr1 = __expf(m1 - mn1);
        float rs0 = 0.f, rs1 = 0.f;
        #pragma unroll
        for (int j = 0; j < 8; j++) {
            uint32_t u0 = f2tf32(__expf(s[j][0] - mn0));
            uint32_t u1 = f2tf32(__expf(s[j][1] - mn0));
            uint32_t u2 = f2tf32(__expf(s[j][2] - mn1));
            uint32_t u3 = f2tf32(__expf(s[j][3] - mn1));
            rs0 += __uint_as_float(u0) + __uint_as_float(u1);
            rs1 += __uint_as_float(u2) + __uint_as_float(u3);
            int base_g  = (qr0 + g) * (PS2_STRIDE * 2) + j * 8;
            int base_g8 = (qr0 + g + 8) * (PS2_STRIDE * 2) + j * 8;
            Psw[base_g  + poff0]     = u0;
            Psw[base_g  + poff0 + 2] = u1;
            Psw[base_g8 + poff0]     = u2;
            Psw[base_g8 + poff0 + 2] = u3;
        }
        #pragma unroll
        for (int off = 1; off <= 2; off <<= 1) {
            rs0 += __shfl_xor_sync(0xffffffffu, rs0, off);
            rs1 += __shfl_xor_sync(0xffffffffu, rs1, off);
        }
        l0 = l0 * cr0 + rs0;  m0 = mn0;
        l1 = l1 * cr1 + rs1;  m1 = mn1;
        #pragma unroll
        for (int j = 0; j < 16; j++) {
            o[j][0] *= cr0; o[j][1] *= cr0;
            o[j][2] *= cr1; o[j][3] *= cr1;
        }
        __syncwarp();

        #pragma unroll
        for (int ks = 0; ks < 8; ks++) {
            uint2 pg  = Ps2[(qr0 + g) * PS2_STRIDE + ks * 4 + t];
            uint2 pg8 = Ps2[(qr0 + g + 8) * PS2_STRIDE + ks * 4 + t];
            #pragma unroll
            for (int j = 0; j < 16; j++) {
                uint2 vb = Vs2[(ks * 4 + t) * VS2_STRIDE + j * 8 + g];
                mma_tf32(o[j][0], o[j][1], o[j][2], o[j][3],
                         pg.x, pg8.x, pg.y, pg8.y, vb.x, vb.y);
            }
        }
    }

    float inv0 = 1.f / l0, inv1 = 1.f / l1;
    float* op = out + (size_t)(b * T + q0) * H;
    #pragma unroll
    for (int j = 0; j < 16; j++) {
        int col = j * 8 + 2 * t;
        *(float2*)&op[(qr0 + g) * H + col] =
            make_float2(o[j][0] * inv0, o[j][1] * inv0);
        *(float2*)&op[(qr0 + g + 8) * H + col] =
            make_float2(o[j][2] * inv1, o[j][3] * inv1);
    }
}

// ---------------------------------------------------------------------------
// Inputs (metadata order): x, Wk, Wq, Wv. Output: [8,2048,128] fp32.
// ---------------------------------------------------------------------------
extern "C" void kernel_launch(void* const* d_in, const int* in_sizes, int n_in,
                              void* d_out, int out_size)
{
    const float* x  = (const float*)d_in[0];
    const float* Wk = (const float*)d_in[1];
    const float* Wq = (const float*)d_in[2];
    const float* Wv = (const float*)d_in[3];
    float* out = (float*)d_out;

    cudaFuncSetAttribute(proj_kernel,
                         cudaFuncAttributeMaxDynamicSharedMemorySize,
                         PJ_SMEM_BYTES);
    cudaFuncSetAttribute(attn_kernel,
                         cudaFuncAttributeMaxDynamicSharedMemorySize,
                         ATTN_SMEM_BYTES);

    proj_kernel<<<dim3(BT / 128, 3), 256, PJ_SMEM_BYTES>>>(x, Wq, Wk, Wv);
    attn_kernel<<<dim3(T / 128, B), 256, ATTN_SMEM_BYTES>>>(out);
}

// round 17
// speedup vs baseline: 1.9161x; 1.9161x over previous
#include <cuda_runtime.h>
#include <cuda_fp16.h>
#include <stdint.h>
#include <math.h>

#define B   8
#define T   2048
#define EMB 1024
#define H   128
#define BT  (B*T)

// Scratch for Q/K/V projections, now fp16 (no cudaMalloc allowed).
__device__ __half g_q[BT * H];
__device__ __half g_k[BT * H];
__device__ __half g_v[BT * H];

// ---------------------------------------------------------------------------
// Helpers
// ---------------------------------------------------------------------------
__device__ __forceinline__ uint32_t f2tf32(float f) {
    uint32_t u;
    asm volatile("cvt.rna.tf32.f32 %0, %1;" : "=r"(u) : "f"(f));
    return u;
}

__device__ __forceinline__ uint32_t prmt(uint32_t a, uint32_t b, uint32_t sel) {
    uint32_t r;
    asm("prmt.b32 %0, %1, %2, %3;" : "=r"(r) : "r"(a), "r"(b), "r"(sel));
    return r;
}

__device__ __forceinline__ uint32_t h2u(__half2 h) {
    return *(uint32_t*)&h;
}

__device__ __forceinline__ void mma_tf32(
    float& d0, float& d1, float& d2, float& d3,
    uint32_t a0, uint32_t a1, uint32_t a2, uint32_t a3,
    uint32_t b0, uint32_t b1)
{
    asm volatile(
        "mma.sync.aligned.m16n8k8.row.col.f32.tf32.tf32.f32 "
        "{%0,%1,%2,%3}, {%4,%5,%6,%7}, {%8,%9}, {%0,%1,%2,%3};"
        : "+f"(d0), "+f"(d1), "+f"(d2), "+f"(d3)
        : "r"(a0), "r"(a1), "r"(a2), "r"(a3), "r"(b0), "r"(b1));
}

__device__ __forceinline__ void mma_f16(
    float& d0, float& d1, float& d2, float& d3,
    uint32_t a0, uint32_t a1, uint32_t a2, uint32_t a3,
    uint32_t b0, uint32_t b1)
{
    asm volatile(
        "mma.sync.aligned.m16n8k16.row.col.f32.f16.f16.f32 "
        "{%0,%1,%2,%3}, {%4,%5,%6,%7}, {%8,%9}, {%0,%1,%2,%3};"
        : "+f"(d0), "+f"(d1), "+f"(d2), "+f"(d3)
        : "r"(a0), "r"(a1), "r"(a2), "r"(a3), "r"(b0), "r"(b1));
}

// ---------------------------------------------------------------------------
// Projection GEMM (tf32 mma, PROVEN R11/R14 internals): fp16 OUTPUT only change.
// CTA tile 128x128, BK=32, 256 threads = 8 warps (4 M x 2 N), double-buffered.
// ---------------------------------------------------------------------------
#define XS2_STRIDE 20
#define WS2_STRIDE 132
#define PJ_XS  (128 * XS2_STRIDE)
#define PJ_WS  (16 * WS2_STRIDE)
#define PJ_BUF (PJ_XS + PJ_WS)
#define PJ_SMEM_BYTES (2 * PJ_BUF * 8)

__global__ __launch_bounds__(256) void proj_kernel(
    const float* __restrict__ x,
    const float* __restrict__ Wq,
    const float* __restrict__ Wk,
    const float* __restrict__ Wv)
{
    extern __shared__ uint2 psm[];

    const float* __restrict__ W;
    __half* out;
    if (blockIdx.y == 0)      { W = Wq; out = g_q; }
    else if (blockIdx.y == 1) { W = Wk; out = g_k; }
    else                      { W = Wv; out = g_v; }

    const int row0 = blockIdx.x * 128;
    const int tid  = threadIdx.x;
    const int warp = tid >> 5, lane = tid & 31;
    const int g = lane >> 2, t = lane & 3;
    const int wm = warp >> 1, wn = warp & 1;

    float4 rx[2][2];
    float4 rw[2][2];

    const int xr0  = tid >> 2,  xksg = tid & 3;
    const int xr1  = (tid + 256) >> 2;
    const int wpr0 = tid >> 5,  wn40 = (tid & 31) * 4;
    const int wpr1 = (tid + 256) >> 5;

    auto prefetch = [&](int kk) {
        const float* s0 = &x[(size_t)(row0 + xr0) * EMB + kk + xksg * 8];
        rx[0][0] = *(const float4*)s0;
        rx[0][1] = *(const float4*)(s0 + 4);
        const float* s1 = &x[(size_t)(row0 + xr1) * EMB + kk + xksg * 8];
        rx[1][0] = *(const float4*)s1;
        rx[1][1] = *(const float4*)(s1 + 4);
        {
            int ks = wpr0 >> 2, tt = wpr0 & 3;
            const float* w0 = &W[(size_t)(kk + ks * 8 + tt) * H + wn40];
            rw[0][0] = *(const float4*)w0;
            rw[0][1] = *(const float4*)(w0 + 4 * H);
        }
        {
            int ks = wpr1 >> 2, tt = wpr1 & 3;
            const float* w1 = &W[(size_t)(kk + ks * 8 + tt) * H + wn40];
            rw[1][0] = *(const float4*)w1;
            rw[1][1] = *(const float4*)(w1 + 4 * H);
        }
    };

    auto sts_chunk = [&](int buf) {
        uint2* xs = psm + buf * PJ_BUF;
        uint2* ws = xs + PJ_XS;
        {
            uint2* dst = &xs[xr0 * XS2_STRIDE + xksg * 4];
            dst[0] = make_uint2(f2tf32(rx[0][0].x), f2tf32(rx[0][1].x));
            dst[1] = make_uint2(f2tf32(rx[0][0].y), f2tf32(rx[0][1].y));
            dst[2] = make_uint2(f2tf32(rx[0][0].z), f2tf32(rx[0][1].z));
            dst[3] = make_uint2(f2tf32(rx[0][0].w), f2tf32(rx[0][1].w));
            dst = &xs[xr1 * XS2_STRIDE + xksg * 4];
            dst[0] = make_uint2(f2tf32(rx[1][0].x), f2tf32(rx[1][1].x));
            dst[1] = make_uint2(f2tf32(rx[1][0].y), f2tf32(rx[1][1].y));
            dst[2] = make_uint2(f2tf32(rx[1][0].z), f2tf32(rx[1][1].z));
            dst[3] = make_uint2(f2tf32(rx[1][0].w), f2tf32(rx[1][1].w));
        }
        {
            uint2* dst = &ws[wpr0 * WS2_STRIDE + wn40];
            dst[0] = make_uint2(f2tf32(rw[0][0].x), f2tf32(rw[0][1].x));
            dst[1] = make_uint2(f2tf32(rw[0][0].y), f2tf32(rw[0][1].y));
            dst[2] = make_uint2(f2tf32(rw[0][0].z), f2tf32(rw[0][1].z));
            dst[3] = make_uint2(f2tf32(rw[0][0].w), f2tf32(rw[0][1].w));
            dst = &ws[wpr1 * WS2_STRIDE + wn40];
            dst[0] = make_uint2(f2tf32(rw[1][0].x), f2tf32(rw[1][1].x));
            dst[1] = make_uint2(f2tf32(rw[1][0].y), f2tf32(rw[1][1].y));
            dst[2] = make_uint2(f2tf32(rw[1][0].z), f2tf32(rw[1][1].z));
            dst[3] = make_uint2(f2tf32(rw[1][0].w), f2tf32(rw[1][1].w));
        }
    };

    float c[2][8][4];
    #pragma unroll
    for (int i = 0; i < 2; i++)
        #pragma unroll
        for (int j = 0; j < 8; j++)
            c[i][j][0] = c[i][j][1] = c[i][j][2] = c[i][j][3] = 0.f;

    prefetch(0);
    sts_chunk(0);
    __syncthreads();

    for (int cidx = 0; cidx < 32; cidx++) {
        if (cidx < 31) prefetch((cidx + 1) * 32);

        uint2* xs = psm + (cidx & 1) * PJ_BUF;
        uint2* ws = xs + PJ_XS;
        #pragma unroll
        for (int ks = 0; ks < 4; ks++) {
            uint2 A[2][2];
            #pragma unroll
            for (int i = 0; i < 2; i++) {
                int rb = wm * 32 + i * 16;
                A[i][0] = xs[(rb + g) * XS2_STRIDE + ks * 4 + t];
                A[i][1] = xs[(rb + g + 8) * XS2_STRIDE + ks * 4 + t];
            }
            #pragma unroll
            for (int j = 0; j < 8; j++) {
                uint2 bb = ws[(ks * 4 + t) * WS2_STRIDE + wn * 64 + j * 8 + g];
                #pragma unroll
                for (int i = 0; i < 2; i++)
                    mma_tf32(c[i][j][0], c[i][j][1], c[i][j][2], c[i][j][3],
                             A[i][0].x, A[i][1].x, A[i][0].y, A[i][1].y,
                             bb.x, bb.y);
            }
        }

        if (cidx < 31) {
            sts_chunk((cidx + 1) & 1);
            __syncthreads();
        }
    }

    // fp16 epilogue: cols (2t, 2t+1) adjacent -> one half2 per pair
    #pragma unroll
    for (int i = 0; i < 2; i++) {
        int r = row0 + wm * 32 + i * 16 + g;
        #pragma unroll
        for (int j = 0; j < 8; j++) {
            int w = wn * 32 + j * 4 + t;   // half2 word index within row
            ((__half2*)(out + (size_t)r * H))[w] =
                __floats2half2_rn(c[i][j][0], c[i][j][1]);
            ((__half2*)(out + (size_t)(r + 8) * H))[w] =
                __floats2half2_rn(c[i][j][2], c[i][j][3]);
        }
    }
}

// ---------------------------------------------------------------------------
// Flash attention, fp16 m16n8k16: grid (T/128, B), 256 threads = 8 warps.
// Each warp owns 16 q-rows. Q fragments in regs (staged via smem repack);
// K/V/P in pair-packed fp16 smem; fp32 accumulate + softmax; scale applied
// to S post-MMA.
// ---------------------------------------------------------------------------
#define QS_STRIDE 36     // u2/row: 32 data + 4 pad = 72 words, mod32 = 8
#define KS_STRIDE 36
#define VS_STRIDE 132    // u2/pair-row: 264 words, mod32 = 8
#define PS_STRIDE 20     // u2/row: 16 data + 4 pad = 40 words, mod32 = 8
#define QS_OFF 0
#define KS_OFF (128 * QS_STRIDE)              // 4608
#define VS_OFF (KS_OFF + 64 * KS_STRIDE)      // 6912
#define PS_OFF (VS_OFF + 16 * VS_STRIDE)      // 9024
#define ATTN_U2 (PS_OFF + 128 * PS_STRIDE)    // 11584
#define ATTN_SMEM_BYTES (ATTN_U2 * 8)         // 92672

__global__ __launch_bounds__(256, 1) void attn_kernel(float* __restrict__ out)
{
    extern __shared__ uint2 sm2[];
    uint2* Qs = sm2 + QS_OFF;
    uint2* Ks = sm2 + KS_OFF;
    uint2* Vs = sm2 + VS_OFF;
    uint2* Ps = sm2 + PS_OFF;

    const int b    = blockIdx.y;
    const int q0   = blockIdx.x * 128;
    const int tid  = threadIdx.x;
    const int warp = tid >> 5, lane = tid & 31;
    const int g = lane >> 2, t = lane & 3;
    const int qr0 = warp * 16;
    const float scale = 0.08838834764831845f;   // 1/sqrt(128)

    // ---- Stage Q: pure word repack (halves already paired in memory) ----
    {
        const __half* qp = g_q + (size_t)(b * T + q0) * H;
        #pragma unroll
        for (int p = 0; p < 4; p++) {
            int idx = tid + p * 256;            // 0..1023
            int r = idx >> 3, ks = idx & 7;
            const uint4* s = (const uint4*)((const uint32_t*)(qp + r * H) + ks * 8);
            uint4 w0 = s[0], w1 = s[1];
            uint2* dst = &Qs[r * QS_STRIDE + ks * 4];
            dst[0] = make_uint2(w0.x, w1.x);
            dst[1] = make_uint2(w0.y, w1.y);
            dst[2] = make_uint2(w0.z, w1.z);
            dst[3] = make_uint2(w0.w, w1.w);
        }
    }
    __syncthreads();

    // Q fragments: 8 ksteps x {a0,a1,a2,a3}
    uint32_t qa[8][4];
    #pragma unroll
    for (int ks = 0; ks < 8; ks++) {
        uint2 A0 = Qs[(qr0 + g) * QS_STRIDE + ks * 4 + t];
        uint2 A1 = Qs[(qr0 + g + 8) * QS_STRIDE + ks * 4 + t];
        qa[ks][0] = A0.x; qa[ks][1] = A1.x;
        qa[ks][2] = A0.y; qa[ks][3] = A1.y;
    }

    float o[16][4];
    #pragma unroll
    for (int j = 0; j < 16; j++)
        o[j][0] = o[j][1] = o[j][2] = o[j][3] = 0.f;
    float m0 = -1e30f, m1 = -1e30f, l0 = 0.f, l1 = 0.f;

    for (int t0 = 0; t0 < T; t0 += 64) {
        __syncthreads();   // prev tile reads done (also covers Q-stage reads)
        {
            const __half* kp = g_k + (size_t)(b * T + t0) * H;
            const __half* vp = g_v + (size_t)(b * T + t0) * H;
            // K: 512 slots (key, kstep) -> 2 iters
            #pragma unroll
            for (int p = 0; p < 2; p++) {
                int idx = tid + p * 256;
                int key = idx >> 3, ks = idx & 7;
                const uint4* s = (const uint4*)((const uint32_t*)(kp + key * H) + ks * 8);
                uint4 w0 = s[0], w1 = s[1];
                uint2* dst = &Ks[key * KS_STRIDE + ks * 4];
                dst[0] = make_uint2(w0.x, w1.x);
                dst[1] = make_uint2(w0.y, w1.y);
                dst[2] = make_uint2(w0.z, w1.z);
                dst[3] = make_uint2(w0.w, w1.w);
            }
            // V: 256 slots (pair-row, 8-col group), cross-row prmt interleave
            {
                int pr = tid >> 4;              // 0..15
                int c8 = (tid & 15) * 8;        // halves col base
                int ks2 = pr >> 2, t2 = pr & 3;
                int r2 = 16 * ks2 + 2 * t2;     // first raw key row of b0 pair
                const uint32_t* base = (const uint32_t*)vp + (c8 >> 1);
                uint4 a  = *(const uint4*)(base + (size_t)(r2)     * (H / 2));
                uint4 bq = *(const uint4*)(base + (size_t)(r2 + 1) * (H / 2));
                uint4 cq = *(const uint4*)(base + (size_t)(r2 + 8) * (H / 2));
                uint4 dq = *(const uint4*)(base + (size_t)(r2 + 9) * (H / 2));
                uint2* dst = &Vs[pr * VS_STRIDE + c8];
                dst[0] = make_uint2(prmt(a.x, bq.x, 0x5410), prmt(cq.x, dq.x, 0x5410));
                dst[1] = make_uint2(prmt(a.x, bq.x, 0x7632), prmt(cq.x, dq.x, 0x7632));
                dst[2] = make_uint2(prmt(a.y, bq.y, 0x5410), prmt(cq.y, dq.y, 0x5410));
                dst[3] = make_uint2(prmt(a.y, bq.y, 0x7632), prmt(cq.y, dq.y, 0x7632));
                dst[4] = make_uint2(prmt(a.z, bq.z, 0x5410), prmt(cq.z, dq.z, 0x5410));
                dst[5] = make_uint2(prmt(a.z, bq.z, 0x7632), prmt(cq.z, dq.z, 0x7632));
                dst[6] = make_uint2(prmt(a.w, bq.w, 0x5410), prmt(cq.w, dq.w, 0x5410));
                dst[7] = make_uint2(prmt(a.w, bq.w, 0x7632), prmt(cq.w, dq.w, 0x7632));
            }
        }
        __syncthreads();

        // ---- S = Q K^T (8 ksteps of 16) ----
        float s[8][4];
        #pragma unroll
        for (int j = 0; j < 8; j++)
            s[j][0] = s[j][1] = s[j][2] = s[j][3] = 0.f;

        #pragma unroll
        for (int ks = 0; ks < 8; ks++) {
            #pragma unroll
            for (int j = 0; j < 8; j++) {
                uint2 kb = Ks[(j * 8 + g) * KS_STRIDE + ks * 4 + t];
                mma_f16(s[j][0], s[j][1], s[j][2], s[j][3],
                        qa[ks][0], qa[ks][1], qa[ks][2], qa[ks][3],
                        kb.x, kb.y);
            }
        }
        #pragma unroll
        for (int j = 0; j < 8; j++) {
            s[j][0] *= scale; s[j][1] *= scale;
            s[j][2] *= scale; s[j][3] *= scale;
        }

        // ---- online softmax (rows qr0+g, qr0+g+8) ----
        float mx0 = -1e30f, mx1 = -1e30f;
        #pragma unroll
        for (int j = 0; j < 8; j++) {
            mx0 = fmaxf(mx0, fmaxf(s[j][0], s[j][1]));
            mx1 = fmaxf(mx1, fmaxf(s[j][2], s[j][3]));
        }
        #pragma unroll
        for (int off = 1; off <= 2; off <<= 1) {
            mx0 = fmaxf(mx0, __shfl_xor_sync(0xffffffffu, mx0, off));
            mx1 = fmaxf(mx1, __shfl_xor_sync(0xffffffffu, mx1, off));
        }
        float mn0 = fmaxf(m0, mx0), mn1 = fmaxf(m1, mx1);
        float cr0 = __expf(m0 - mn0), cr1 = __expf(m1 - mn1);
        float rs0 = 0.f, rs1 = 0.f;

        // P: half2 packs, {j-even, j-odd} pair-packed per kstep of 16 keys
        #pragma unroll
        for (int ks = 0; ks < 4; ks++) {
            int j0 = 2 * ks, j1 = 2 * ks + 1;
            __half2 he_g  = __floats2half2_rn(__expf(s[j0][0] - mn0), __expf(s[j0][1] - mn0));
            __half2 ho_g  = __floats2half2_rn(__expf(s[j1][0] - mn0), __expf(s[j1][1] - mn0));
            __half2 he_g8 = __floats2half2_rn(__expf(s[j0][2] - mn1), __expf(s[j0][3] - mn1));
            __half2 ho_g8 = __floats2half2_rn(__expf(s[j1][2] - mn1), __expf(s[j1][3] - mn1));
            float2 f;
            f = __half22float2(he_g);  rs0 += f.x + f.y;
            f = __half22float2(ho_g);  rs0 += f.x + f.y;
            f = __half22float2(he_g8); rs1 += f.x + f.y;
            f = __half22float2(ho_g8); rs1 += f.x + f.y;
            Ps[(qr0 + g) * PS_STRIDE + ks * 4 + t]     = make_uint2(h2u(he_g),  h2u(ho_g));
            Ps[(qr0 + g + 8) * PS_STRIDE + ks * 4 + t] = make_uint2(h2u(he_g8), h2u(ho_g8));
        }
        #pragma unroll
        for (int off = 1; off <= 2; off <<= 1) {
            rs0 += __shfl_xor_sync(0xffffffffu, rs0, off);
            rs1 += __shfl_xor_sync(0xffffffffu, rs1, off);
        }
        l0 = l0 * cr0 + rs0;  m0 = mn0;
        l1 = l1 * cr1 + rs1;  m1 = mn1;
        #pragma unroll
        for (int j = 0; j < 16; j++) {
            o[j][0] *= cr0; o[j][1] *= cr0;
            o[j][2] *= cr1; o[j][3] *= cr1;
        }
        __syncwarp();   // P rows are warp-private

        // ---- O += P V (4 ksteps of 16 keys) ----
        #pragma unroll
        for (int ks = 0; ks < 4; ks++) {
            uint2 pg  = Ps[(qr0 + g) * PS_STRIDE + ks * 4 + t];
            uint2 pg8 = Ps[(qr0 + g + 8) * PS_STRIDE + ks * 4 + t];
            #pragma unroll
            for (int j = 0; j < 16; j++) {
                uint2 vb = Vs[(ks * 4 + t) * VS_STRIDE + j * 8 + g];
                mma_f16(o[j][0], o[j][1], o[j][2], o[j][3],
                        pg.x, pg8.x, pg.y, pg8.y, vb.x, vb.y);
            }
        }
    }

    // Epilogue: normalize + fp32 store
    float inv0 = 1.f / l0, inv1 = 1.f / l1;
    float* op = out + (size_t)(b * T + q0) * H;
    #pragma unroll
    for (int j = 0; j < 16; j++) {
        int col = j * 8 + 2 * t;
        *(float2*)&op[(qr0 + g) * H + col] =
            make_float2(o[j][0] * inv0, o[j][1] * inv0);
        *(float2*)&op[(qr0 + g + 8) * H + col] =
            make_float2(o[j][2] * inv1, o[j][3] * inv1);
    }
}

// ---------------------------------------------------------------------------
// Inputs (metadata order): x, Wk, Wq, Wv. Output: [8,2048,128] fp32.
// ---------------------------------------------------------------------------
extern "C" void kernel_launch(void* const* d_in, const int* in_sizes, int n_in,
                              void* d_out, int out_size)
{
    const float* x  = (const float*)d_in[0];
    const float* Wk = (const float*)d_in[1];
    const float* Wq = (const float*)d_in[2];
    const float* Wv = (const float*)d_in[3];
    float* out = (float*)d_out;

    cudaFuncSetAttribute(proj_kernel,
                         cudaFuncAttributeMaxDynamicSharedMemorySize,
                         PJ_SMEM_BYTES);
    cudaFuncSetAttribute(attn_kernel,
                         cudaFuncAttributeMaxDynamicSharedMemorySize,
                         ATTN_SMEM_BYTES);

    proj_kernel<<<dim3(BT / 128, 3), 256, PJ_SMEM_BYTES>>>(x, Wq, Wk, Wv);
    attn_kernel<<<dim3(T / 128, B), 256, ATTN_SMEM_BYTES>>>(out);
}